// round 5
// baseline (speedup 1.0000x reference)
#include <cuda_runtime.h>
#include <cuda_bf16.h>
#include <cstdint>
#include <cstddef>

#define NMAX 50000
#define EMAX 800000
#define DIN 96
#define DOUT 256

// ---------------- scratch (__device__ globals; no allocs allowed) ----------
__device__ int   g_counts[NMAX];
__device__ int   g_rowstart[NMAX + 1];
__device__ int   g_cursor[NMAX];
__device__ int   g_esrc[EMAX];
__device__ float g_eval[EMAX];
__device__ __nv_bfloat16 g_aext0[(size_t)NMAX * (2 * DIN)];    // [N][192] = [hi96|lo96]
__device__ __nv_bfloat16 g_hext[(size_t)NMAX * (2 * DOUT)];    // [N][512] = [hi256|lo256]
__device__ __nv_bfloat16 g_b0ext[DOUT * (3 * DIN)];            // [256][288] = [hi|hi|lo]
__device__ __nv_bfloat16 g_b1ext[DOUT * (3 * DOUT)];           // [256][768] = [hi|hi|lo]

// ---------------- helpers ---------------------------------------------------
__device__ __forceinline__ uint32_t smem_u32(const void* p) {
    uint32_t a;
    asm("{ .reg .u64 t; cvta.to.shared.u64 t, %1; cvt.u32.u64 %0, t; }"
        : "=r"(a) : "l"(p));
    return a;
}
__device__ __forceinline__ void ldsm4(uint32_t* r, uint32_t addr) {
    asm volatile("ldmatrix.sync.aligned.m8n8.x4.shared.b16 {%0,%1,%2,%3}, [%4];"
                 : "=r"(r[0]), "=r"(r[1]), "=r"(r[2]), "=r"(r[3]) : "r"(addr));
}
__device__ __forceinline__ void mma16816(float* c, const uint32_t* a, const uint32_t* b) {
    asm volatile(
        "mma.sync.aligned.m16n8k16.row.col.f32.bf16.bf16.f32 "
        "{%0,%1,%2,%3}, {%4,%5,%6,%7}, {%8,%9}, {%0,%1,%2,%3};"
        : "+f"(c[0]), "+f"(c[1]), "+f"(c[2]), "+f"(c[3])
        : "r"(a[0]), "r"(a[1]), "r"(a[2]), "r"(a[3]), "r"(b[0]), "r"(b[1]));
}
__device__ __forceinline__ uint32_t split_pack_hi(float v0, float v1,
                                                  uint32_t& lo_out) {
    __nv_bfloat16 h0 = __float2bfloat16(v0);
    __nv_bfloat16 h1 = __float2bfloat16(v1);
    __nv_bfloat16 l0 = __float2bfloat16(v0 - __bfloat162float(h0));
    __nv_bfloat16 l1 = __float2bfloat16(v1 - __bfloat162float(h1));
    __nv_bfloat162 hp; hp.x = h0; hp.y = h1;
    __nv_bfloat162 lp; lp.x = l0; lp.y = l1;
    lo_out = *(uint32_t*)&lp;
    return *(uint32_t*)&hp;
}

// ---------------------------------------------------------------------------
// CSR build: histogram -> scan -> fill
// ---------------------------------------------------------------------------
__global__ void zero_counts_kernel(int n) {
    int i = blockIdx.x * blockDim.x + threadIdx.x;
    if (i < n) g_counts[i] = 0;
}
__global__ void hist_kernel(const int* __restrict__ dst, int E) {
    int e = blockIdx.x * blockDim.x + threadIdx.x;
    if (e < E) atomicAdd(&g_counts[dst[e]], 1);
}
// single-block exclusive scan over counts[N] -> rowstart[N+1], cursor[N]
__global__ void __launch_bounds__(1024) scan_kernel(int N) {
    __shared__ int ssum[1024];
    const int t = threadIdx.x;
    const int chunk = (N + 1023) / 1024;
    const int beg = t * chunk;
    const int end = min(beg + chunk, N);
    int s = 0;
    for (int i = beg; i < end; i++) s += g_counts[i];
    ssum[t] = s;
    __syncthreads();
    // Hillis-Steele inclusive scan
    for (int d = 1; d < 1024; d <<= 1) {
        int v = (t >= d) ? ssum[t - d] : 0;
        __syncthreads();
        ssum[t] += v;
        __syncthreads();
    }
    int off = (t == 0) ? 0 : ssum[t - 1];
    for (int i = beg; i < end; i++) {
        g_rowstart[i] = off;
        g_cursor[i] = off;
        off += g_counts[i];
    }
    if (end == N && beg <= N) g_rowstart[N] = off;
}
__global__ void fill_kernel(const int* __restrict__ src,
                            const int* __restrict__ dst,
                            const float* __restrict__ vals, int E) {
    int e = blockIdx.x * blockDim.x + threadIdx.x;
    if (e < E) {
        int pos = atomicAdd(&g_cursor[dst[e]], 1);
        g_esrc[pos] = src[e];
        g_eval[pos] = vals[e];
    }
}

// ---------------------------------------------------------------------------
// Gather SpMM: warp per node. agg = sum v*x[src] + eps*x[node],
// written directly as bf16 [hi|lo] into aext0. Lane owns cols {l, l+32, l+64}.
// ---------------------------------------------------------------------------
__global__ void __launch_bounds__(256)
gather_kernel(const float* __restrict__ x, const float* __restrict__ eps,
              __nv_bfloat16* __restrict__ aext, int N) {
    const int warp = (blockIdx.x * blockDim.x + threadIdx.x) >> 5;
    if (warp >= N) return;
    const int lane = threadIdx.x & 31;
    const int beg = g_rowstart[warp];
    const int end = g_rowstart[warp + 1];

    float a0 = 0.f, a1 = 0.f, a2 = 0.f;
    if (beg < end) {
        int s = g_esrc[beg];
        float v = g_eval[beg];
        for (int e = beg; e < end; e++) {
            const float* xr = x + (size_t)s * DIN;
            float x0 = xr[lane], x1 = xr[lane + 32], x2 = xr[lane + 64];
            if (e + 1 < end) { s = g_esrc[e + 1]; v2_next:; }
            float vn = (e + 1 < end) ? g_eval[e + 1] : 0.f;
            a0 = fmaf(v, x0, a0);
            a1 = fmaf(v, x1, a1);
            a2 = fmaf(v, x2, a2);
            v = vn;
        }
    }
    // eps residual
    {
        const float* xd = x + (size_t)warp * DIN;
        float e0 = eps[0];
        a0 = fmaf(e0, xd[lane], a0);
        a1 = fmaf(e0, xd[lane + 32], a1);
        a2 = fmaf(e0, xd[lane + 64], a2);
    }
    // split + write
    __nv_bfloat16* row = aext + (size_t)warp * (2 * DIN);
    __nv_bfloat16 h;
    h = __float2bfloat16(a0); row[lane]      = h; row[DIN + lane]      = __float2bfloat16(a0 - __bfloat162float(h));
    h = __float2bfloat16(a1); row[lane + 32] = h; row[DIN + lane + 32] = __float2bfloat16(a1 - __bfloat162float(h));
    h = __float2bfloat16(a2); row[lane + 64] = h; row[DIN + lane + 64] = __float2bfloat16(a2 - __bfloat162float(h));
}

// W fp32 [K][256] -> Bext bf16 [256][3K] = [hi|hi|lo] transposed
__global__ void wsplit_kernel(const float* __restrict__ W,
                              __nv_bfloat16* __restrict__ Bext, int K) {
    int i = blockIdx.x * blockDim.x + threadIdx.x;
    if (i < K * DOUT) {
        int k = i / DOUT, n = i - k * DOUT;
        float v = W[i];
        __nv_bfloat16 h = __float2bfloat16(v);
        __nv_bfloat16 l = __float2bfloat16(v - __bfloat162float(h));
        size_t base = (size_t)n * (3 * K);
        Bext[base + k] = h;
        Bext[base + K + k] = h;
        Bext[base + 2 * K + k] = l;
    }
}

// ---------------------------------------------------------------------------
// bf16 HMMA GEMM with extended K (error-split encoded in K dimension).
// ---------------------------------------------------------------------------
#define STG_BYTES (128 * 80)

template <int MODE, int KP, int WRAP>
__global__ void __launch_bounds__(256)
gemm_mma(const __nv_bfloat16* __restrict__ Aext,
         const __nv_bfloat16* __restrict__ Bext,
         float* __restrict__ Cf, __nv_bfloat16* __restrict__ Cext, int M,
         const float* __restrict__ gamma, const float* __restrict__ beta,
         const float* __restrict__ mean, const float* __restrict__ var) {
    __shared__ __align__(16) unsigned char sA[2][STG_BYTES];
    __shared__ __align__(16) unsigned char sB[2][STG_BYTES];
    __shared__ float s_sc[128], s_bi[128];

    const int tid = threadIdx.x;
    const int wid = tid >> 5, lane = tid & 31;
    const int mBlock = blockIdx.y * 128, nBlock = blockIdx.x * 128;
    const int wm = wid & 3, wn = wid >> 2;
    const int tq = lane >> 2, tr = lane & 3;

    const uint32_t aBase = smem_u32(sA);
    const uint32_t bBase = smem_u32(sB);

    const int ldrow = tid >> 2;
    const int ldkc = tid & 3;

    const int arow = ((lane >> 3) & 1) * 8 + (lane & 7);
    const int akb = (lane >> 4) * 8;
    const int brow = ((lane >> 4) & 1) * 8 + (lane & 7);
    const int bkb = ((lane >> 3) & 1) * 8;
    const uint32_t aAddr0 = aBase + (uint32_t)(wm * 32 + arow) * 80 + akb * 2;
    const uint32_t bAddr0 = bBase + (uint32_t)(wn * 64 + brow) * 80 + bkb * 2;

    float acc[2][8][4];
#pragma unroll
    for (int i = 0; i < 2; i++)
#pragma unroll
        for (int j = 0; j < 8; j++)
#pragma unroll
            for (int q = 0; q < 4; q++) acc[i][j][q] = 0.f;

    constexpr int NS = KP / 32;

    auto issue = [&](int ks, int stage) {
        const int k0 = ks * 32;
        const int ksA = (k0 >= WRAP) ? k0 - WRAP : k0;
#pragma unroll
        for (int i = 0; i < 2; i++) {
            int row = ldrow + i * 64;
            uint32_t sa = aBase + stage * STG_BYTES + row * 80 + ldkc * 16;
            const void* ga = Aext + (size_t)(mBlock + row) * WRAP + ksA + ldkc * 8;
            int sz = (mBlock + row < M) ? 16 : 0;
            asm volatile("cp.async.cg.shared.global [%0], [%1], 16, %2;"
                         :: "r"(sa), "l"(ga), "r"(sz) : "memory");
            uint32_t sb = bBase + stage * STG_BYTES + row * 80 + ldkc * 16;
            const void* gb = Bext + (size_t)(nBlock + row) * KP + k0 + ldkc * 8;
            asm volatile("cp.async.cg.shared.global [%0], [%1], 16;"
                         :: "r"(sb), "l"(gb) : "memory");
        }
        asm volatile("cp.async.commit_group;" ::: "memory");
    };

    issue(0, 0);

    for (int ks = 0; ks < NS; ks++) {
        const int st = ks & 1;
        if (ks + 1 < NS) {
            issue(ks + 1, st ^ 1);
            asm volatile("cp.async.wait_group 1;" ::: "memory");
        } else {
            asm volatile("cp.async.wait_group 0;" ::: "memory");
        }
        __syncthreads();

        const uint32_t aS = aAddr0 + st * STG_BYTES;
        const uint32_t bS = bAddr0 + st * STG_BYTES;
#pragma unroll
        for (int ksub = 0; ksub < 2; ksub++) {
            uint32_t a[2][4];
#pragma unroll
            for (int mt = 0; mt < 2; mt++)
                ldsm4(a[mt], aS + mt * (16 * 80) + ksub * 32);
            uint32_t b[8][2];
#pragma unroll
            for (int np = 0; np < 4; np++) {
                uint32_t t[4];
                ldsm4(t, bS + np * (16 * 80) + ksub * 32);
                b[2 * np][0] = t[0]; b[2 * np][1] = t[1];
                b[2 * np + 1][0] = t[2]; b[2 * np + 1][1] = t[3];
            }
#pragma unroll
            for (int mt = 0; mt < 2; mt++)
#pragma unroll
                for (int nt = 0; nt < 8; nt++)
                    mma16816(acc[mt][nt], a[mt], b[nt]);
        }
        __syncthreads();
    }

    if (MODE == 0) {
        if (tid < 128) {
            int col = nBlock + tid;
            float s = gamma[col] * rsqrtf(var[col] + 1e-3f);
            s_sc[tid] = s;
            s_bi[tid] = beta[col] - mean[col] * s;
        }
        __syncthreads();
    }

#pragma unroll
    for (int mt = 0; mt < 2; mt++) {
        const int m0 = mBlock + wm * 32 + mt * 16 + tq;
#pragma unroll
        for (int nt = 0; nt < 8; nt++) {
            const int cloc = wn * 64 + nt * 8 + 2 * tr;
            const int col = nBlock + cloc;
            float* c = acc[mt][nt];
            if (MODE == 0) {
                float s0 = s_sc[cloc], s1 = s_sc[cloc + 1];
                float b0 = s_bi[cloc], b1 = s_bi[cloc + 1];
                if (m0 < M) {
                    float v0 = fmaxf(fmaf(c[0], s0, b0), 0.f);
                    float v1 = fmaxf(fmaf(c[1], s1, b1), 0.f);
                    uint32_t lo, hi = split_pack_hi(v0, v1, lo);
                    size_t base = (size_t)m0 * (2 * DOUT) + col;
                    *(uint32_t*)(Cext + base) = hi;
                    *(uint32_t*)(Cext + base + DOUT) = lo;
                }
                if (m0 + 8 < M) {
                    float v0 = fmaxf(fmaf(c[2], s0, b0), 0.f);
                    float v1 = fmaxf(fmaf(c[3], s1, b1), 0.f);
                    uint32_t lo, hi = split_pack_hi(v0, v1, lo);
                    size_t base = (size_t)(m0 + 8) * (2 * DOUT) + col;
                    *(uint32_t*)(Cext + base) = hi;
                    *(uint32_t*)(Cext + base + DOUT) = lo;
                }
            } else {
                if (m0 < M)
                    *(float2*)(Cf + (size_t)m0 * DOUT + col) =
                        make_float2(c[0], c[1]);
                if (m0 + 8 < M)
                    *(float2*)(Cf + (size_t)(m0 + 8) * DOUT + col) =
                        make_float2(c[2], c[3]);
            }
        }
    }
}

// ---------------------------------------------------------------------------
extern "C" void kernel_launch(void* const* d_in, const int* in_sizes, int n_in,
                              void* d_out, int out_size) {
    const float* x     = (const float*)d_in[0];
    const int*   src   = (const int*)d_in[1];
    const int*   dst   = (const int*)d_in[2];
    const float* vals  = (const float*)d_in[3];
    const float* eps   = (const float*)d_in[4];
    const float* W0    = (const float*)d_in[5];
    const float* W1    = (const float*)d_in[6];
    const float* gamma = (const float*)d_in[7];
    const float* beta  = (const float*)d_in[8];
    const float* mean  = (const float*)d_in[9];
    const float* var   = (const float*)d_in[10];

    int N = in_sizes[0] / DIN;
    int E = in_sizes[1];

    __nv_bfloat16 *aext0, *hext, *b0ext, *b1ext;
    cudaGetSymbolAddress((void**)&aext0, g_aext0);
    cudaGetSymbolAddress((void**)&hext, g_hext);
    cudaGetSymbolAddress((void**)&b0ext, g_b0ext);
    cudaGetSymbolAddress((void**)&b1ext, g_b1ext);

    // weight transpose + split (tiny)
    wsplit_kernel<<<(DIN * DOUT + 255) / 256, 256>>>(W0, b0ext, DIN);
    wsplit_kernel<<<(DOUT * DOUT + 255) / 256, 256>>>(W1, b1ext, DOUT);

    // CSR build
    zero_counts_kernel<<<(N + 255) / 256, 256>>>(N);
    hist_kernel<<<(E + 255) / 256, 256>>>(dst, E);
    scan_kernel<<<1, 1024>>>(N);
    fill_kernel<<<(E + 255) / 256, 256>>>(src, dst, vals, E);

    // gather SpMM + eps residual + bf16 split, fused
    int warps = N;
    gather_kernel<<<(warps * 32 + 255) / 256, 256>>>(x, eps, aext0, N);

    // GEMM0: h(hi|lo) = relu(bn(agg @ W0))   (K' = 288, wrap 192)
    dim3 grid(DOUT / 128, (N + 127) / 128);
    gemm_mma<0, 3 * DIN, 2 * DIN><<<grid, 256>>>(
        aext0, b0ext, nullptr, hext, N, gamma, beta, mean, var);

    // GEMM1: out = h @ W1                    (K' = 768, wrap 512)
    gemm_mma<1, 3 * DOUT, 2 * DOUT><<<grid, 256>>>(
        hext, b1ext, (float*)d_out, nullptr, N,
        nullptr, nullptr, nullptr, nullptr);
}

// round 6
// speedup vs baseline: 1.2158x; 1.2158x over previous
#include <cuda_runtime.h>
#include <cuda_bf16.h>
#include <cstdint>
#include <cstddef>

#define NMAX 50000
#define DIN 96
#define DOUT 256

// ---------------- scratch (__device__ globals; no allocs allowed) ----------
__device__ float g_agg[(size_t)NMAX * DIN];
__device__ __nv_bfloat16 g_aext0[(size_t)NMAX * (2 * DIN)];    // [N][192] = [hi96|lo96]
__device__ __nv_bfloat16 g_hext[(size_t)NMAX * (2 * DOUT)];    // [N][512] = [hi256|lo256]
__device__ __nv_bfloat16 g_b0ext[DOUT * (3 * DIN)];            // [256][288] = [hi|hi|lo]
__device__ __nv_bfloat16 g_b1ext[DOUT * (3 * DOUT)];           // [256][768] = [hi|hi|lo]

// ---------------- helpers ---------------------------------------------------
__device__ __forceinline__ uint32_t smem_u32(const void* p) {
    uint32_t a;
    asm("{ .reg .u64 t; cvta.to.shared.u64 t, %1; cvt.u32.u64 %0, t; }"
        : "=r"(a) : "l"(p));
    return a;
}
__device__ __forceinline__ void ldsm4(uint32_t* r, uint32_t addr) {
    asm volatile("ldmatrix.sync.aligned.m8n8.x4.shared.b16 {%0,%1,%2,%3}, [%4];"
                 : "=r"(r[0]), "=r"(r[1]), "=r"(r[2]), "=r"(r[3]) : "r"(addr));
}
__device__ __forceinline__ void mma16816(float* c, const uint32_t* a, const uint32_t* b) {
    asm volatile(
        "mma.sync.aligned.m16n8k16.row.col.f32.bf16.bf16.f32 "
        "{%0,%1,%2,%3}, {%4,%5,%6,%7}, {%8,%9}, {%0,%1,%2,%3};"
        : "+f"(c[0]), "+f"(c[1]), "+f"(c[2]), "+f"(c[3])
        : "r"(a[0]), "r"(a[1]), "r"(a[2]), "r"(a[3]), "r"(b[0]), "r"(b[1]));
}
__device__ __forceinline__ uint32_t split_pack_hi(float v0, float v1,
                                                  uint32_t& lo_out) {
    __nv_bfloat16 h0 = __float2bfloat16(v0);
    __nv_bfloat16 h1 = __float2bfloat16(v1);
    __nv_bfloat16 l0 = __float2bfloat16(v0 - __bfloat162float(h0));
    __nv_bfloat16 l1 = __float2bfloat16(v1 - __bfloat162float(h1));
    __nv_bfloat162 hp; hp.x = h0; hp.y = h1;
    __nv_bfloat162 lp; lp.x = l0; lp.y = l1;
    lo_out = *(uint32_t*)&lp;
    return *(uint32_t*)&hp;
}

// ---------------------------------------------------------------------------
// agg = eps * x
// ---------------------------------------------------------------------------
__global__ void init_agg_kernel(const float* __restrict__ x,
                                const float* __restrict__ eps, int n4) {
    int i = blockIdx.x * blockDim.x + threadIdx.x;
    if (i < n4) {
        float e = eps[0];
        float4 v = ((const float4*)x)[i];
        v.x *= e; v.y *= e; v.z *= e; v.w *= e;
        ((float4*)g_agg)[i] = v;
    }
}

// ---------------------------------------------------------------------------
// agg[dst] += vals[e] * x[src] via red.global.add.v4.f32
// ---------------------------------------------------------------------------
__global__ void spmm_kernel(const float* __restrict__ x,
                            const int* __restrict__ src,
                            const int* __restrict__ dst,
                            const float* __restrict__ vals, int total) {
    int idx = blockIdx.x * blockDim.x + threadIdx.x;
    if (idx >= total) return;
    int e = idx / 24;
    int c = idx - e * 24;
    int s = src[e];
    int d = dst[e];
    float v = vals[e];
    float4 xv = *(const float4*)(x + (size_t)s * DIN + c * 4);
    float* p = g_agg + (size_t)d * DIN + c * 4;
    asm volatile("red.global.add.v4.f32 [%0], {%1,%2,%3,%4};"
                 :: "l"(p), "f"(v * xv.x), "f"(v * xv.y),
                    "f"(v * xv.z), "f"(v * xv.w) : "memory");
}

// ---------------------------------------------------------------------------
// agg fp32 [N][96] -> aext0 bf16 [N][192] = [hi|lo]
// ---------------------------------------------------------------------------
__global__ void split_agg_kernel(const float* __restrict__ src,
                                 __nv_bfloat16* __restrict__ dstp, int n) {
    int i = blockIdx.x * blockDim.x + threadIdx.x;
    if (i < n) {
        int row = i / DIN, k = i - row * DIN;
        float v = src[i];
        __nv_bfloat16 h = __float2bfloat16(v);
        dstp[(size_t)row * (2 * DIN) + k] = h;
        dstp[(size_t)row * (2 * DIN) + DIN + k] =
            __float2bfloat16(v - __bfloat162float(h));
    }
}

// W fp32 [K][256] -> Bext bf16 [256][3K] = [hi|hi|lo] transposed
__global__ void wsplit_kernel(const float* __restrict__ W,
                              __nv_bfloat16* __restrict__ Bext, int K) {
    int i = blockIdx.x * blockDim.x + threadIdx.x;
    if (i < K * DOUT) {
        int k = i / DOUT, n = i - k * DOUT;
        float v = W[i];
        __nv_bfloat16 h = __float2bfloat16(v);
        __nv_bfloat16 l = __float2bfloat16(v - __bfloat162float(h));
        size_t base = (size_t)n * (3 * K);
        Bext[base + k] = h;
        Bext[base + K + k] = h;
        Bext[base + 2 * K + k] = l;
    }
}

// ---------------------------------------------------------------------------
// bf16 HMMA GEMM, extended K, 3-stage cp.async multistage pipeline.
//   C[M,256] tile 128x128, 8 warps (4x2), warp tile 32x64, mma m16n8k16.
//   A: [M][WRAP] bf16, logical K' = KP with wrap (error-split in K)
//   B: [256][KP] bf16 (n-major, k contiguous)
//   MODE 0: BN+ReLU epilogue, write Cext [M][2*DOUT] = [hi|lo]
//   MODE 1: plain epilogue, write fp32 Cf [M][256]
// ---------------------------------------------------------------------------
#define STG_BYTES (128 * 80)
#define NSTAGE 3
#define OFF_B (NSTAGE * STG_BYTES)
#define OFF_SC (2 * NSTAGE * STG_BYTES)
#define OFF_BI (OFF_SC + 512)
#define GEMM_SMEM (OFF_BI + 512)

template <int MODE, int KP, int WRAP>
__global__ void __launch_bounds__(256)
gemm_mma(const __nv_bfloat16* __restrict__ Aext,
         const __nv_bfloat16* __restrict__ Bext,
         float* __restrict__ Cf, __nv_bfloat16* __restrict__ Cext, int M,
         const float* __restrict__ gamma, const float* __restrict__ beta,
         const float* __restrict__ mean, const float* __restrict__ var) {
    extern __shared__ __align__(16) unsigned char smem[];

    const int tid = threadIdx.x;
    const int wid = tid >> 5, lane = tid & 31;
    const int mBlock = blockIdx.y * 128, nBlock = blockIdx.x * 128;
    const int wm = wid & 3, wn = wid >> 2;
    const int tq = lane >> 2, tr = lane & 3;

    const uint32_t aBase = smem_u32(smem);
    const uint32_t bBase = aBase + OFF_B;
    float* s_sc = (float*)(smem + OFF_SC);
    float* s_bi = (float*)(smem + OFF_BI);

    const int ldrow = tid >> 2;
    const int ldkc = tid & 3;

    const int arow = ((lane >> 3) & 1) * 8 + (lane & 7);
    const int akb = (lane >> 4) * 8;
    const int brow = ((lane >> 4) & 1) * 8 + (lane & 7);
    const int bkb = ((lane >> 3) & 1) * 8;
    const uint32_t aAddr0 = aBase + (uint32_t)(wm * 32 + arow) * 80 + akb * 2;
    const uint32_t bAddr0 = bBase + (uint32_t)(wn * 64 + brow) * 80 + bkb * 2;

    float acc[2][8][4];
#pragma unroll
    for (int i = 0; i < 2; i++)
#pragma unroll
        for (int j = 0; j < 8; j++)
#pragma unroll
            for (int q = 0; q < 4; q++) acc[i][j][q] = 0.f;

    constexpr int NS = KP / 32;

    auto issue = [&](int ks, int stage) {
        const int k0 = ks * 32;
        const int ksA = (k0 >= WRAP) ? k0 - WRAP : k0;
#pragma unroll
        for (int i = 0; i < 2; i++) {
            int row = ldrow + i * 64;
            uint32_t sa = aBase + stage * STG_BYTES + row * 80 + ldkc * 16;
            const void* ga = Aext + (size_t)(mBlock + row) * WRAP + ksA + ldkc * 8;
            int sz = (mBlock + row < M) ? 16 : 0;
            asm volatile("cp.async.cg.shared.global [%0], [%1], 16, %2;"
                         :: "r"(sa), "l"(ga), "r"(sz) : "memory");
            uint32_t sb = bBase + stage * STG_BYTES + row * 80 + ldkc * 16;
            const void* gb = Bext + (size_t)(nBlock + row) * KP + k0 + ldkc * 8;
            asm volatile("cp.async.cg.shared.global [%0], [%1], 16;"
                         :: "r"(sb), "l"(gb) : "memory");
        }
        asm volatile("cp.async.commit_group;" ::: "memory");
    };

    // prologue: fill stages 0..NSTAGE-2
    issue(0, 0);
    if (NS > 1) issue(1, 1);

    for (int ks = 0; ks < NS; ks++) {
        // stage ks must be resident; keep 1 group in flight except at the tail
        if (ks + 1 < NS) {
            asm volatile("cp.async.wait_group 1;" ::: "memory");
        } else {
            asm volatile("cp.async.wait_group 0;" ::: "memory");
        }
        __syncthreads();
        // all warps have finished compute(ks-1) -> safe to refill its stage
        if (ks + NSTAGE - 1 < NS)
            issue(ks + NSTAGE - 1, (ks + NSTAGE - 1) % NSTAGE);

        const int st = ks % NSTAGE;
        const uint32_t aS = aAddr0 + st * STG_BYTES;
        const uint32_t bS = bAddr0 + st * STG_BYTES;
#pragma unroll
        for (int ksub = 0; ksub < 2; ksub++) {
            uint32_t a[2][4];
#pragma unroll
            for (int mt = 0; mt < 2; mt++)
                ldsm4(a[mt], aS + mt * (16 * 80) + ksub * 32);
            uint32_t b[8][2];
#pragma unroll
            for (int np = 0; np < 4; np++) {
                uint32_t t[4];
                ldsm4(t, bS + np * (16 * 80) + ksub * 32);
                b[2 * np][0] = t[0]; b[2 * np][1] = t[1];
                b[2 * np + 1][0] = t[2]; b[2 * np + 1][1] = t[3];
            }
#pragma unroll
            for (int mt = 0; mt < 2; mt++)
#pragma unroll
                for (int nt = 0; nt < 8; nt++)
                    mma16816(acc[mt][nt], a[mt], b[nt]);
        }
    }
    __syncthreads();

    if (MODE == 0) {
        if (tid < 128) {
            int col = nBlock + tid;
            float s = gamma[col] * rsqrtf(var[col] + 1e-3f);
            s_sc[tid] = s;
            s_bi[tid] = beta[col] - mean[col] * s;
        }
        __syncthreads();
    }

#pragma unroll
    for (int mt = 0; mt < 2; mt++) {
        const int m0 = mBlock + wm * 32 + mt * 16 + tq;
#pragma unroll
        for (int nt = 0; nt < 8; nt++) {
            const int cloc = wn * 64 + nt * 8 + 2 * tr;
            const int col = nBlock + cloc;
            float* c = acc[mt][nt];
            if (MODE == 0) {
                float s0 = s_sc[cloc], s1 = s_sc[cloc + 1];
                float b0 = s_bi[cloc], b1 = s_bi[cloc + 1];
                if (m0 < M) {
                    float v0 = fmaxf(fmaf(c[0], s0, b0), 0.f);
                    float v1 = fmaxf(fmaf(c[1], s1, b1), 0.f);
                    uint32_t lo, hi = split_pack_hi(v0, v1, lo);
                    size_t base = (size_t)m0 * (2 * DOUT) + col;
                    *(uint32_t*)(Cext + base) = hi;
                    *(uint32_t*)(Cext + base + DOUT) = lo;
                }
                if (m0 + 8 < M) {
                    float v0 = fmaxf(fmaf(c[2], s0, b0), 0.f);
                    float v1 = fmaxf(fmaf(c[3], s1, b1), 0.f);
                    uint32_t lo, hi = split_pack_hi(v0, v1, lo);
                    size_t base = (size_t)(m0 + 8) * (2 * DOUT) + col;
                    *(uint32_t*)(Cext + base) = hi;
                    *(uint32_t*)(Cext + base + DOUT) = lo;
                }
            } else {
                if (m0 < M)
                    *(float2*)(Cf + (size_t)m0 * DOUT + col) =
                        make_float2(c[0], c[1]);
                if (m0 + 8 < M)
                    *(float2*)(Cf + (size_t)(m0 + 8) * DOUT + col) =
                        make_float2(c[2], c[3]);
            }
        }
    }
}

// ---------------------------------------------------------------------------
extern "C" void kernel_launch(void* const* d_in, const int* in_sizes, int n_in,
                              void* d_out, int out_size) {
    const float* x     = (const float*)d_in[0];
    const int*   src   = (const int*)d_in[1];
    const int*   dst   = (const int*)d_in[2];
    const float* vals  = (const float*)d_in[3];
    const float* eps   = (const float*)d_in[4];
    const float* W0    = (const float*)d_in[5];
    const float* W1    = (const float*)d_in[6];
    const float* gamma = (const float*)d_in[7];
    const float* beta  = (const float*)d_in[8];
    const float* mean  = (const float*)d_in[9];
    const float* var   = (const float*)d_in[10];

    int N = in_sizes[0] / DIN;
    int E = in_sizes[1];

    float* agg;            cudaGetSymbolAddress((void**)&agg, g_agg);
    __nv_bfloat16 *aext0, *hext, *b0ext, *b1ext;
    cudaGetSymbolAddress((void**)&aext0, g_aext0);
    cudaGetSymbolAddress((void**)&hext, g_hext);
    cudaGetSymbolAddress((void**)&b0ext, g_b0ext);
    cudaGetSymbolAddress((void**)&b1ext, g_b1ext);

    cudaFuncSetAttribute(gemm_mma<0, 3 * DIN, 2 * DIN>,
                         cudaFuncAttributeMaxDynamicSharedMemorySize, GEMM_SMEM);
    cudaFuncSetAttribute(gemm_mma<1, 3 * DOUT, 2 * DOUT>,
                         cudaFuncAttributeMaxDynamicSharedMemorySize, GEMM_SMEM);

    // weight transpose + split (tiny, independent)
    wsplit_kernel<<<(DIN * DOUT + 255) / 256, 256>>>(W0, b0ext, DIN);
    wsplit_kernel<<<(DOUT * DOUT + 255) / 256, 256>>>(W1, b1ext, DOUT);

    // 1. agg = eps * x
    int n4 = N * (DIN / 4);
    init_agg_kernel<<<(n4 + 255) / 256, 256>>>(x, eps, n4);

    // 2. scatter-add edge messages
    int total = E * (DIN / 4);
    spmm_kernel<<<(total + 255) / 256, 256>>>(x, src, dst, vals, total);

    // 3. split agg -> bf16 [hi|lo]
    int nel = N * DIN;
    split_agg_kernel<<<(nel + 255) / 256, 256>>>(agg, aext0, nel);

    // 4. h(hi|lo) = relu(bn(agg @ W0))   (K' = 288, wrap 192)
    dim3 grid(DOUT / 128, (N + 127) / 128);
    gemm_mma<0, 3 * DIN, 2 * DIN><<<grid, 256, GEMM_SMEM>>>(
        aext0, b0ext, nullptr, hext, N, gamma, beta, mean, var);

    // 5. out = h @ W1                    (K' = 768, wrap 512)
    gemm_mma<1, 3 * DOUT, 2 * DOUT><<<grid, 256, GEMM_SMEM>>>(
        hext, b1ext, (float*)d_out, nullptr, N,
        nullptr, nullptr, nullptr, nullptr);
}

// round 7
// speedup vs baseline: 1.6229x; 1.3349x over previous
#include <cuda_runtime.h>
#include <cuda_fp16.h>
#include <cstdint>
#include <cstddef>

#define NMAX 50000
#define DIN 96
#define DOUT 256

// ---------------- scratch (__device__ globals; no allocs allowed) ----------
__device__ float  g_agg[(size_t)NMAX * DIN];
__device__ __half g_a16[(size_t)NMAX * DIN];        // fp16 agg [N][96]
__device__ __half g_h16[(size_t)NMAX * DOUT];       // fp16 h   [N][256]
__device__ __half g_b0ext[DOUT * (2 * DIN)];        // [256][192] = [W0h|W0l] (transposed)
__device__ __half g_b1ext[DOUT * (2 * DOUT)];       // [256][512] = [W1h|W1l] (transposed)

// ---------------- helpers ---------------------------------------------------
__device__ __forceinline__ uint32_t smem_u32(const void* p) {
    uint32_t a;
    asm("{ .reg .u64 t; cvta.to.shared.u64 t, %1; cvt.u32.u64 %0, t; }"
        : "=r"(a) : "l"(p));
    return a;
}
__device__ __forceinline__ void ldsm4(uint32_t* r, uint32_t addr) {
    asm volatile("ldmatrix.sync.aligned.m8n8.x4.shared.b16 {%0,%1,%2,%3}, [%4];"
                 : "=r"(r[0]), "=r"(r[1]), "=r"(r[2]), "=r"(r[3]) : "r"(addr));
}
__device__ __forceinline__ void mma16816(float* c, const uint32_t* a, const uint32_t* b) {
    asm volatile(
        "mma.sync.aligned.m16n8k16.row.col.f32.f16.f16.f32 "
        "{%0,%1,%2,%3}, {%4,%5,%6,%7}, {%8,%9}, {%0,%1,%2,%3};"
        : "+f"(c[0]), "+f"(c[1]), "+f"(c[2]), "+f"(c[3])
        : "r"(a[0]), "r"(a[1]), "r"(a[2]), "r"(a[3]), "r"(b[0]), "r"(b[1]));
}

// ---------------------------------------------------------------------------
// agg = eps * x
// ---------------------------------------------------------------------------
__global__ void init_agg_kernel(const float* __restrict__ x,
                                const float* __restrict__ eps, int n4) {
    int i = blockIdx.x * blockDim.x + threadIdx.x;
    if (i < n4) {
        float e = eps[0];
        float4 v = ((const float4*)x)[i];
        v.x *= e; v.y *= e; v.z *= e; v.w *= e;
        ((float4*)g_agg)[i] = v;
    }
}

// ---------------------------------------------------------------------------
// agg[dst] += vals[e] * x[src] via red.global.add.v4.f32
// ---------------------------------------------------------------------------
__global__ void spmm_kernel(const float* __restrict__ x,
                            const int* __restrict__ src,
                            const int* __restrict__ dst,
                            const float* __restrict__ vals, int total) {
    int idx = blockIdx.x * blockDim.x + threadIdx.x;
    if (idx >= total) return;
    int e = idx / 24;
    int c = idx - e * 24;
    int s = src[e];
    int d = dst[e];
    float v = vals[e];
    float4 xv = *(const float4*)(x + (size_t)s * DIN + c * 4);
    float* p = g_agg + (size_t)d * DIN + c * 4;
    asm volatile("red.global.add.v4.f32 [%0], {%1,%2,%3,%4};"
                 :: "l"(p), "f"(v * xv.x), "f"(v * xv.y),
                    "f"(v * xv.z), "f"(v * xv.w) : "memory");
}

// ---------------------------------------------------------------------------
// agg fp32 -> fp16 (elementwise, vectorized)
// ---------------------------------------------------------------------------
__global__ void cvt_agg_kernel(const float* __restrict__ src,
                               __half* __restrict__ dstp, int n4) {
    int i = blockIdx.x * blockDim.x + threadIdx.x;
    if (i < n4) {
        float4 v = ((const float4*)src)[i];
        __half2 a = __floats2half2_rn(v.x, v.y);
        __half2 b = __floats2half2_rn(v.z, v.w);
        ((uint2*)dstp)[i] = make_uint2(*(uint32_t*)&a, *(uint32_t*)&b);
    }
}

// ---------------------------------------------------------------------------
// Both weights: fp32 W[K][256] -> Bext fp16 [256][2K] = [Wh|Wl] transposed
// ---------------------------------------------------------------------------
__global__ void wsplit_kernel(const float* __restrict__ W0,
                              const float* __restrict__ W1,
                              __half* __restrict__ B0,
                              __half* __restrict__ B1) {
    int i = blockIdx.x * blockDim.x + threadIdx.x;
    const int n0 = DIN * DOUT;
    if (i < n0) {
        int k = i / DOUT, n = i - k * DOUT;
        float v = W0[i];
        __half h = __float2half_rn(v);
        size_t base = (size_t)n * (2 * DIN);
        B0[base + k] = h;
        B0[base + DIN + k] = __float2half_rn(v - __half2float(h));
    } else if (i < n0 + DOUT * DOUT) {
        int j = i - n0;
        int k = j / DOUT, n = j - k * DOUT;
        float v = W1[j];
        __half h = __float2half_rn(v);
        size_t base = (size_t)n * (2 * DOUT);
        B1[base + k] = h;
        B1[base + DOUT + k] = __float2half_rn(v - __half2float(h));
    }
}

// ---------------------------------------------------------------------------
// fp16 HMMA GEMM, extended K (weight hi/lo in K), 3-stage cp.async pipeline.
//   C[M,256] tile 128x128, 8 warps (4x2), warp tile 32x64, mma m16n8k16.
//   A: [M][WRAP] fp16, logical K' = KP, A wraps (same data for both halves)
//   B: [256][KP] fp16 = [Wh|Wl] (n-major, k contiguous)
//   MODE 0: BN+ReLU epilogue, write fp16 Ch [M][256]
//   MODE 1: plain epilogue, write fp32 Cf [M][256]
// ---------------------------------------------------------------------------
#define STG_BYTES (128 * 80)
#define NSTAGE 3
#define OFF_B (NSTAGE * STG_BYTES)
#define OFF_SC (2 * NSTAGE * STG_BYTES)
#define OFF_BI (OFF_SC + 512)
#define GEMM_SMEM (OFF_BI + 512)

template <int MODE, int KP, int WRAP>
__global__ void __launch_bounds__(256)
gemm_mma(const __half* __restrict__ Aext,
         const __half* __restrict__ Bext,
         float* __restrict__ Cf, __half* __restrict__ Ch, int M,
         const float* __restrict__ gamma, const float* __restrict__ beta,
         const float* __restrict__ mean, const float* __restrict__ var) {
    extern __shared__ __align__(16) unsigned char smem[];

    const int tid = threadIdx.x;
    const int wid = tid >> 5, lane = tid & 31;
    const int mBlock = blockIdx.y * 128, nBlock = blockIdx.x * 128;
    const int wm = wid & 3, wn = wid >> 2;
    const int tq = lane >> 2, tr = lane & 3;

    const uint32_t aBase = smem_u32(smem);
    const uint32_t bBase = aBase + OFF_B;
    float* s_sc = (float*)(smem + OFF_SC);
    float* s_bi = (float*)(smem + OFF_BI);

    const int ldrow = tid >> 2;
    const int ldkc = tid & 3;

    const int arow = ((lane >> 3) & 1) * 8 + (lane & 7);
    const int akb = (lane >> 4) * 8;
    const int brow = ((lane >> 4) & 1) * 8 + (lane & 7);
    const int bkb = ((lane >> 3) & 1) * 8;
    const uint32_t aAddr0 = aBase + (uint32_t)(wm * 32 + arow) * 80 + akb * 2;
    const uint32_t bAddr0 = bBase + (uint32_t)(wn * 64 + brow) * 80 + bkb * 2;

    float acc[2][8][4];
#pragma unroll
    for (int i = 0; i < 2; i++)
#pragma unroll
        for (int j = 0; j < 8; j++)
#pragma unroll
            for (int q = 0; q < 4; q++) acc[i][j][q] = 0.f;

    constexpr int NS = KP / 32;

    auto issue = [&](int ks, int stage) {
        const int k0 = ks * 32;
        const int ksA = (k0 >= WRAP) ? k0 - WRAP : k0;
#pragma unroll
        for (int i = 0; i < 2; i++) {
            int row = ldrow + i * 64;
            uint32_t sa = aBase + stage * STG_BYTES + row * 80 + ldkc * 16;
            const void* ga = Aext + (size_t)(mBlock + row) * WRAP + ksA + ldkc * 8;
            int sz = (mBlock + row < M) ? 16 : 0;
            asm volatile("cp.async.cg.shared.global [%0], [%1], 16, %2;"
                         :: "r"(sa), "l"(ga), "r"(sz) : "memory");
            uint32_t sb = bBase + stage * STG_BYTES + row * 80 + ldkc * 16;
            const void* gb = Bext + (size_t)(nBlock + row) * KP + k0 + ldkc * 8;
            asm volatile("cp.async.cg.shared.global [%0], [%1], 16;"
                         :: "r"(sb), "l"(gb) : "memory");
        }
        asm volatile("cp.async.commit_group;" ::: "memory");
    };

    issue(0, 0);
    if (NS > 1) issue(1, 1);

    for (int ks = 0; ks < NS; ks++) {
        if (ks + 1 < NS) {
            asm volatile("cp.async.wait_group 1;" ::: "memory");
        } else {
            asm volatile("cp.async.wait_group 0;" ::: "memory");
        }
        __syncthreads();
        if (ks + NSTAGE - 1 < NS)
            issue(ks + NSTAGE - 1, (ks + NSTAGE - 1) % NSTAGE);

        const int st = ks % NSTAGE;
        const uint32_t aS = aAddr0 + st * STG_BYTES;
        const uint32_t bS = bAddr0 + st * STG_BYTES;
#pragma unroll
        for (int ksub = 0; ksub < 2; ksub++) {
            uint32_t a[2][4];
#pragma unroll
            for (int mt = 0; mt < 2; mt++)
                ldsm4(a[mt], aS + mt * (16 * 80) + ksub * 32);
            uint32_t b[8][2];
#pragma unroll
            for (int np = 0; np < 4; np++) {
                uint32_t t[4];
                ldsm4(t, bS + np * (16 * 80) + ksub * 32);
                b[2 * np][0] = t[0]; b[2 * np][1] = t[1];
                b[2 * np + 1][0] = t[2]; b[2 * np + 1][1] = t[3];
            }
#pragma unroll
            for (int mt = 0; mt < 2; mt++)
#pragma unroll
                for (int nt = 0; nt < 8; nt++)
                    mma16816(acc[mt][nt], a[mt], b[nt]);
        }
    }
    __syncthreads();

    if (MODE == 0) {
        if (tid < 128) {
            int col = nBlock + tid;
            float s = gamma[col] * rsqrtf(var[col] + 1e-3f);
            s_sc[tid] = s;
            s_bi[tid] = beta[col] - mean[col] * s;
        }
        __syncthreads();
    }

#pragma unroll
    for (int mt = 0; mt < 2; mt++) {
        const int m0 = mBlock + wm * 32 + mt * 16 + tq;
#pragma unroll
        for (int nt = 0; nt < 8; nt++) {
            const int cloc = wn * 64 + nt * 8 + 2 * tr;
            const int col = nBlock + cloc;
            float* c = acc[mt][nt];
            if (MODE == 0) {
                float s0 = s_sc[cloc], s1 = s_sc[cloc + 1];
                float b0 = s_bi[cloc], b1 = s_bi[cloc + 1];
                if (m0 < M) {
                    float v0 = fmaxf(fmaf(c[0], s0, b0), 0.f);
                    float v1 = fmaxf(fmaf(c[1], s1, b1), 0.f);
                    __half2 p = __floats2half2_rn(v0, v1);
                    *(__half2*)(Ch + (size_t)m0 * DOUT + col) = p;
                }
                if (m0 + 8 < M) {
                    float v0 = fmaxf(fmaf(c[2], s0, b0), 0.f);
                    float v1 = fmaxf(fmaf(c[3], s1, b1), 0.f);
                    __half2 p = __floats2half2_rn(v0, v1);
                    *(__half2*)(Ch + (size_t)(m0 + 8) * DOUT + col) = p;
                }
            } else {
                if (m0 < M)
                    *(float2*)(Cf + (size_t)m0 * DOUT + col) =
                        make_float2(c[0], c[1]);
                if (m0 + 8 < M)
                    *(float2*)(Cf + (size_t)(m0 + 8) * DOUT + col) =
                        make_float2(c[2], c[3]);
            }
        }
    }
}

// ---------------------------------------------------------------------------
extern "C" void kernel_launch(void* const* d_in, const int* in_sizes, int n_in,
                              void* d_out, int out_size) {
    const float* x     = (const float*)d_in[0];
    const int*   src   = (const int*)d_in[1];
    const int*   dst   = (const int*)d_in[2];
    const float* vals  = (const float*)d_in[3];
    const float* eps   = (const float*)d_in[4];
    const float* W0    = (const float*)d_in[5];
    const float* W1    = (const float*)d_in[6];
    const float* gamma = (const float*)d_in[7];
    const float* beta  = (const float*)d_in[8];
    const float* mean  = (const float*)d_in[9];
    const float* var   = (const float*)d_in[10];

    int N = in_sizes[0] / DIN;
    int E = in_sizes[1];

    float* agg;            cudaGetSymbolAddress((void**)&agg, g_agg);
    __half *a16, *h16, *b0ext, *b1ext;
    cudaGetSymbolAddress((void**)&a16, g_a16);
    cudaGetSymbolAddress((void**)&h16, g_h16);
    cudaGetSymbolAddress((void**)&b0ext, g_b0ext);
    cudaGetSymbolAddress((void**)&b1ext, g_b1ext);

    cudaFuncSetAttribute(gemm_mma<0, 2 * DIN, DIN>,
                         cudaFuncAttributeMaxDynamicSharedMemorySize, GEMM_SMEM);
    cudaFuncSetAttribute(gemm_mma<1, 2 * DOUT, DOUT>,
                         cudaFuncAttributeMaxDynamicSharedMemorySize, GEMM_SMEM);

    // weight transpose + hi/lo split (one small launch)
    int wtot = DIN * DOUT + DOUT * DOUT;
    wsplit_kernel<<<(wtot + 255) / 256, 256>>>(W0, W1, b0ext, b1ext);

    // 1. agg = eps * x
    int n4 = N * (DIN / 4);
    init_agg_kernel<<<(n4 + 255) / 256, 256>>>(x, eps, n4);

    // 2. scatter-add edge messages
    int total = E * (DIN / 4);
    spmm_kernel<<<(total + 255) / 256, 256>>>(x, src, dst, vals, total);

    // 3. agg -> fp16
    cvt_agg_kernel<<<(n4 + 255) / 256, 256>>>(agg, a16, n4);

    // 4. h = relu(bn(agg @ W0))   (K' = 192, wrap 96)
    dim3 grid(DOUT / 128, (N + 127) / 128);
    gemm_mma<0, 2 * DIN, DIN><<<grid, 256, GEMM_SMEM>>>(
        a16, b0ext, nullptr, h16, N, gamma, beta, mean, var);

    // 5. out = h @ W1             (K' = 512, wrap 256)
    gemm_mma<1, 2 * DOUT, DOUT><<<grid, 256, GEMM_SMEM>>>(
        h16, b1ext, (float*)d_out, nullptr, N,
        nullptr, nullptr, nullptr, nullptr);
}